// round 8
// baseline (speedup 1.0000x reference)
#include <cuda_runtime.h>

// Problem dims (fixed per reference)
#define TT 512
#define BB 64
#define II 768
#define DD 2048
#define LEAK 0.5f

// Stage-2 persistent-kernel config
#define S2_NCTA 128           // 2048 / 16 d-tiles; <=148 SMs -> persistent
#define S2_DTILE 16
#define S2_KT 64
#define S2_THREADS 256
#define S2_NCHUNK (DD / S2_KT)

// Scratch (__device__ globals; no allocations allowed)
__device__ float g_hT[2][DD * BB];      // hidden state TRANSPOSED: [d][b], double-buffered
__device__ float g_Wt[DD * DD];         // res_w transposed: Wt[k][d] = res_w[d][k]  (16 MB)
__device__ unsigned int g_bar[TT];      // per-step grid-barrier counters

// ---------------------------------------------------------------------------
// Packed f32x2 helpers (Blackwell dual-lane fp32 FMA: 2x fp32 throughput)
// ---------------------------------------------------------------------------
__device__ __forceinline__ void ffma2(unsigned long long& acc,
                                      unsigned long long a,
                                      unsigned long long b) {
    asm("fma.rn.f32x2 %0, %1, %2, %0;" : "+l"(acc) : "l"(a), "l"(b));
}
__device__ __forceinline__ unsigned long long pack2(float x) {
    unsigned long long r; unsigned int u = __float_as_uint(x);
    asm("mov.b64 %0, {%1, %2};" : "=l"(r) : "r"(u), "r"(u));
    return r;
}
__device__ __forceinline__ void unpack2(unsigned long long v, float& lo, float& hi) {
    unsigned int a, b;
    asm("mov.b64 {%0, %1}, %2;" : "=r"(a), "=r"(b) : "l"(v));
    lo = __uint_as_float(a); hi = __uint_as_float(b);
}

__device__ __forceinline__ float fast_tanh(float x) {
    // 1 - 2/(e^{2x}+1): exact +/-1 at saturation
    float e = __expf(2.0f * x);
    return 1.0f - 2.0f / (e + 1.0f);
}

// ---------------------------------------------------------------------------
// Init: zero h0 (both buffers) and barrier counters — every replay
// ---------------------------------------------------------------------------
__global__ void init_kernel() {
    int idx = blockIdx.x * blockDim.x + threadIdx.x;
    int stride = gridDim.x * blockDim.x;
    float* h = (float*)g_hT;
    for (int i = idx; i < 2 * DD * BB; i += stride) h[i] = 0.0f;
    for (int i = idx; i < TT; i += stride) g_bar[i] = 0u;
}

// ---------------------------------------------------------------------------
// Transpose res_w [d][k] -> g_Wt [k][d]  (32x32 tiled)
// ---------------------------------------------------------------------------
__global__ __launch_bounds__(256) void transpose_kernel(const float* __restrict__ W) {
    __shared__ float tile[32][33];
    const int bk = blockIdx.x * 32;   // k-block
    const int bd = blockIdx.y * 32;   // d-block
    const int tx = threadIdx.x & 31;
    const int ty = threadIdx.x >> 5;  // 0..7
#pragma unroll
    for (int i = 0; i < 32; i += 8)
        tile[ty + i][tx] = W[(size_t)(bd + ty + i) * DD + bk + tx];
    __syncthreads();
#pragma unroll
    for (int i = 0; i < 32; i += 8)
        g_Wt[(size_t)(bk + ty + i) * DD + bd + tx] = tile[tx][ty + i];
}

// ---------------------------------------------------------------------------
// Stage 1: proj[t,b,n] = sum_k batch[t,b,k]*W_in[n,k] + bias[n], into out[b,t,n]
// CTA tile 64m x 128n, k-tile 16, 256 threads, microtile 4m x 8n via f32x2.
// ---------------------------------------------------------------------------
__global__ __launch_bounds__(256) void proj_kernel(
    const float* __restrict__ A,      // [TT*BB, II]
    const float* __restrict__ W,      // [DD, II]
    const float* __restrict__ bias,
    float* __restrict__ out)          // [BB, TT, DD]
{
    __shared__ __align__(16) float As[16][68];    // [k][m]
    __shared__ __align__(16) float Bs[16][136];   // [k][n]

    const int m0 = blockIdx.y * 64;     // = t * 64 (m-tile == BB)
    const int n0 = blockIdx.x * 128;
    const int tid = threadIdx.x;
    const int tn = tid & 15;            // n-group: 8 n each
    const int tm = tid >> 4;            // m-group: 4 m each

    // loaders
    const int am = tid >> 2, aq = tid & 3;   // A: m row, k-quad
    const int bn = tid >> 1, br = tid & 1;   // B: n row, k-oct

    unsigned long long acc[4][4];
#pragma unroll
    for (int i = 0; i < 4; i++)
#pragma unroll
        for (int j = 0; j < 4; j++) acc[i][j] = 0ull;

    const float* Aptr = A + (size_t)(m0 + am) * II + aq * 4;
    const float* Wptr = W + (size_t)(n0 + bn) * II + br * 8;

    float4 a_reg  = *(const float4*)(Aptr);
    float4 b_reg0 = *(const float4*)(Wptr);
    float4 b_reg1 = *(const float4*)(Wptr + 4);

    for (int k0 = 0; k0 < II; k0 += 16) {
        As[aq * 4 + 0][am] = a_reg.x;
        As[aq * 4 + 1][am] = a_reg.y;
        As[aq * 4 + 2][am] = a_reg.z;
        As[aq * 4 + 3][am] = a_reg.w;
        Bs[br * 8 + 0][bn] = b_reg0.x;
        Bs[br * 8 + 1][bn] = b_reg0.y;
        Bs[br * 8 + 2][bn] = b_reg0.z;
        Bs[br * 8 + 3][bn] = b_reg0.w;
        Bs[br * 8 + 4][bn] = b_reg1.x;
        Bs[br * 8 + 5][bn] = b_reg1.y;
        Bs[br * 8 + 6][bn] = b_reg1.z;
        Bs[br * 8 + 7][bn] = b_reg1.w;
        __syncthreads();

        if (k0 + 16 < II) {
            a_reg  = *(const float4*)(Aptr + k0 + 16);
            b_reg0 = *(const float4*)(Wptr + k0 + 16);
            b_reg1 = *(const float4*)(Wptr + k0 + 20);
        }

#pragma unroll
        for (int k = 0; k < 16; k++) {
            float4 av = *(const float4*)&As[k][tm * 4];
            unsigned long long ap[4];
            ap[0] = pack2(av.x); ap[1] = pack2(av.y);
            ap[2] = pack2(av.z); ap[3] = pack2(av.w);
            ulonglong2 bv0 = *(const ulonglong2*)&Bs[k][tn * 8];
            ulonglong2 bv1 = *(const ulonglong2*)&Bs[k][tn * 8 + 4];
#pragma unroll
            for (int i = 0; i < 4; i++) {
                ffma2(acc[i][0], ap[i], bv0.x);
                ffma2(acc[i][1], ap[i], bv0.y);
                ffma2(acc[i][2], ap[i], bv1.x);
                ffma2(acc[i][3], ap[i], bv1.y);
            }
        }
        __syncthreads();
    }

    // epilogue: m = t*BB + b, t constant per CTA
    const int t = blockIdx.y;
    const int nb = n0 + tn * 8;
    float bia[8];
#pragma unroll
    for (int j = 0; j < 8; j++) bia[j] = bias[nb + j];

#pragma unroll
    for (int i = 0; i < 4; i++) {
        int b = tm * 4 + i;
        float o[8];
        unpack2(acc[i][0], o[0], o[1]);
        unpack2(acc[i][1], o[2], o[3]);
        unpack2(acc[i][2], o[4], o[5]);
        unpack2(acc[i][3], o[6], o[7]);
#pragma unroll
        for (int j = 0; j < 8; j++) o[j] += bia[j];
        float4* dst = (float4*)&out[((size_t)b * TT + t) * DD + nb];
        dst[0] = make_float4(o[0], o[1], o[2], o[3]);
        dst[1] = make_float4(o[4], o[5], o[6], o[7]);
    }
}

// ---------------------------------------------------------------------------
// Stage 2: persistent recurrence. 128 CTAs x 256 threads, d-tile 16.
// h stored transposed [d][b]; W pre-transposed [k][d] with {w,w} duplication
// in smem so the inner loop is: LDS.128(h quad) + LDS.64(w pair) + 2 FFMA2.
// Double-buffered smem -> ONE __syncthreads per 64-k chunk.
// ---------------------------------------------------------------------------
__global__ __launch_bounds__(S2_THREADS) void recur_kernel(float* __restrict__ out)
{
    __shared__ __align__(16) float  Hs[2][S2_KT][BB];          // 32 KB
    __shared__ __align__(16) float2 Ws2[2][S2_KT][S2_DTILE];   // 16 KB

    const int tid = threadIdx.x;
    const int dd  = tid & 15;           // d within tile (also w-loader column)
    const int bq  = tid >> 4;           // batch quad id 0..15
    const int d0  = blockIdx.x * S2_DTILE;
    const int d   = d0 + dd;
    const int b4  = bq * 4;

    // staging coords: f = tid + i*256 -> k = (tid>>4) + i*16, col = tid&15
    const int sk  = tid >> 4;
    const int hc4 = (tid & 15) * 4;

    for (int t = 0; t < TT; t++) {
        const float* hin = g_hT[t & 1];
        float* hout = g_hT[(t + 1) & 1];

        unsigned long long acc0 = 0ull, acc1 = 0ull;   // 4 b-outputs as 2 pairs

        // prefetch chunk 0
        float4 hreg[4]; float wreg[4];
#pragma unroll
        for (int i = 0; i < 4; i++) {
            int k = sk + i * 16;
            hreg[i] = __ldcg((const float4*)&hin[k * BB + hc4]);
            wreg[i] = __ldg(&g_Wt[(size_t)k * DD + d0 + dd]);
        }

        for (int c = 0; c < S2_NCHUNK; c++) {
            const int p = c & 1;
#pragma unroll
            for (int i = 0; i < 4; i++) {
                int k = sk + i * 16;
                *(float4*)&Hs[p][k][hc4] = hreg[i];
                Ws2[p][k][dd] = make_float2(wreg[i], wreg[i]);
            }
            __syncthreads();

            if (c + 1 < S2_NCHUNK) {
                const int kn = (c + 1) * S2_KT;
#pragma unroll
                for (int i = 0; i < 4; i++) {
                    int k = sk + i * 16;
                    hreg[i] = __ldcg((const float4*)&hin[(kn + k) * BB + hc4]);
                    wreg[i] = __ldg(&g_Wt[(size_t)(kn + k) * DD + d0 + dd]);
                }
            }

#pragma unroll
            for (int kk = 0; kk < S2_KT; kk++) {
                unsigned long long w =
                    *(const unsigned long long*)&Ws2[p][kk][dd];
                ulonglong2 hv = *(const ulonglong2*)&Hs[p][kk][b4];
                ffma2(acc0, hv.x, w);
                ffma2(acc1, hv.y, w);
            }
        }

        // epilogue: x = proj + hW ; h_new = 0.5 h + 0.5 tanh(x)
        float hp[4];
        {
            float4 h4 = __ldcg((const float4*)&hin[d * BB + b4]);
            hp[0] = h4.x; hp[1] = h4.y; hp[2] = h4.z; hp[3] = h4.w;
        }
        float av[4];
        unpack2(acc0, av[0], av[1]);
        unpack2(acc1, av[2], av[3]);

        float hn[4];
#pragma unroll
        for (int i = 0; i < 4; i++) {
            size_t oidx = ((size_t)(b4 + i) * TT + t) * DD + d;
            float x = out[oidx] + av[i];
            float v = (1.0f - LEAK) * hp[i] + LEAK * fast_tanh(x);
            hn[i] = v;
            out[oidx] = v;
        }
        *(float4*)&hout[d * BB + b4] = make_float4(hn[0], hn[1], hn[2], hn[3]);

        // grid-wide barrier (skip after the final step)
        if (t < TT - 1) {
            __threadfence();
            __syncthreads();
            if (tid == 0) {
                atomicAdd(&g_bar[t], 1u);
                volatile unsigned int* bp = &g_bar[t];
                while (*bp < (unsigned)S2_NCTA) { __nanosleep(64); }
            }
            __syncthreads();
        }
    }
}

// ---------------------------------------------------------------------------
// Launch
// ---------------------------------------------------------------------------
extern "C" void kernel_launch(void* const* d_in, const int* in_sizes, int n_in,
                              void* d_out, int out_size) {
    (void)in_sizes; (void)n_in; (void)out_size;
    const float* batch   = (const float*)d_in[0];  // [TT, BB, II]
    const float* input_w = (const float*)d_in[1];  // [DD, II]
    const float* res_w   = (const float*)d_in[2];  // [DD, DD]
    const float* bias    = (const float*)d_in[3];  // [DD]
    float* out = (float*)d_out;                    // [BB, TT, DD]

    init_kernel<<<128, 256>>>();

    dim3 gt(DD / 32, DD / 32);          // 64 x 64
    transpose_kernel<<<gt, 256>>>(res_w);

    dim3 g1(DD / 128, TT);              // 16 x 512
    proj_kernel<<<g1, 256>>>(batch, input_w, bias, out);

    recur_kernel<<<S2_NCTA, S2_THREADS>>>(out);
}